// round 3
// baseline (speedup 1.0000x reference)
#include <cuda_runtime.h>
#include <cstddef>
#include <math.h>

#define B_ 32
#define T_ 512
#define D_ 1024
#define U_ 1024
#define BBU_ 2048
#define NBLK 128
#define NTHR 256
#define KC 64

// ---------------- persistent scratch (device globals; no runtime alloc) ----------------
__device__ float g_xn[B_*T_*D_];      // layernormed x
__device__ float g_cfcx[B_*T_*D_];    // xn @ w_in + b_in
__device__ float g_cfco[B_*T_*U_];    // scan outputs
__device__ float g_h[B_*U_];          // recurrent state
__device__ float g_bb0[B_*BBU_];
__device__ float g_bb1[B_*BBU_];
__device__ unsigned g_bar;            // monotonic grid-barrier counter (memset each launch)

// ---------------- grid barrier (monotonic counter, no reset races) ----------------
__device__ __forceinline__ void grid_bar(unsigned target){
  __syncthreads();
  if (threadIdx.x == 0){
    __threadfence();                       // make our stage writes visible (release)
    atomicAdd(&g_bar, 1u);
    while (*((volatile unsigned*)&g_bar) < target) { __nanosleep(32); }
    __threadfence();                       // gpu-scope fence -> CCTL.IVALL: invalidate L1D (acquire)
  }
  __syncthreads();
}

// ---------------- LayerNorm ----------------
__global__ void k_ln(const float* __restrict__ x, const float* __restrict__ gw,
                     const float* __restrict__ gb){
  int row = blockIdx.x;               // B*T rows
  int tid = threadIdx.x;              // 256 threads, 4 elems each
  const float4* xr = (const float4*)(x + (size_t)row * D_);
  float4 v = xr[tid];
  float s = v.x + v.y + v.z + v.w;
  float q = v.x*v.x + v.y*v.y + v.z*v.z + v.w*v.w;
  #pragma unroll
  for (int o = 16; o > 0; o >>= 1){
    s += __shfl_xor_sync(0xffffffffu, s, o);
    q += __shfl_xor_sync(0xffffffffu, q, o);
  }
  __shared__ float ss[8], sq[8];
  if ((tid & 31) == 0){ ss[tid >> 5] = s; sq[tid >> 5] = q; }
  __syncthreads();
  if (tid == 0){
    float a = 0.f, c = 0.f;
    #pragma unroll
    for (int i = 0; i < 8; i++){ a += ss[i]; c += sq[i]; }
    ss[0] = a; sq[0] = c;
  }
  __syncthreads();
  float mu  = ss[0] * (1.0f / D_);
  float var = sq[0] * (1.0f / D_) - mu * mu;
  float r   = rsqrtf(var + 1e-5f);
  float4 wv = ((const float4*)gw)[tid];
  float4 bv = ((const float4*)gb)[tid];
  float4 o;
  o.x = (v.x - mu) * r * wv.x + bv.x;
  o.y = (v.y - mu) * r * wv.y + bv.y;
  o.z = (v.z - mu) * r * wv.z + bv.z;
  o.w = (v.w - mu) * r * wv.w + bv.w;
  ((float4*)(g_xn + (size_t)row * D_))[tid] = o;
}

// ---------------- generic fp32 SGEMM: C = A[M,K] @ W[K,N] + bias (+res) ----------------
__global__ void __launch_bounds__(256) k_gemm(
    const float* __restrict__ A, const float* __restrict__ W,
    const float* __restrict__ bias, const float* __restrict__ res,
    float* __restrict__ C, int M, int N, int K)
{
  __shared__ float As[16][64];
  __shared__ float Ws[16][64];
  int tid = threadIdx.x;
  int bn = blockIdx.x * 64, bm = blockIdx.y * 64;
  int tx = tid & 15, ty = tid >> 4;
  int lam = tid >> 2, lak = (tid & 3) * 4;   // A loader: row lam (0..63), k lak..lak+3
  int lwk = tid >> 4, lwn = (tid & 15) * 4;  // W loader: row lwk (0..15), col lwn..+3
  float acc[4][4] = {};
  for (int k0 = 0; k0 < K; k0 += 16){
    float4 av = *(const float4*)(A + (size_t)(bm + lam) * K + k0 + lak);
    As[lak+0][lam] = av.x; As[lak+1][lam] = av.y;
    As[lak+2][lam] = av.z; As[lak+3][lam] = av.w;
    *(float4*)&Ws[lwk][lwn] = *(const float4*)(W + (size_t)(k0 + lwk) * N + bn + lwn);
    __syncthreads();
    #pragma unroll
    for (int k = 0; k < 16; k++){
      float4 a4 = *(float4*)&As[k][ty * 4];
      float4 b4 = *(float4*)&Ws[k][tx * 4];
      acc[0][0] = fmaf(a4.x, b4.x, acc[0][0]); acc[0][1] = fmaf(a4.x, b4.y, acc[0][1]);
      acc[0][2] = fmaf(a4.x, b4.z, acc[0][2]); acc[0][3] = fmaf(a4.x, b4.w, acc[0][3]);
      acc[1][0] = fmaf(a4.y, b4.x, acc[1][0]); acc[1][1] = fmaf(a4.y, b4.y, acc[1][1]);
      acc[1][2] = fmaf(a4.y, b4.z, acc[1][2]); acc[1][3] = fmaf(a4.y, b4.w, acc[1][3]);
      acc[2][0] = fmaf(a4.z, b4.x, acc[2][0]); acc[2][1] = fmaf(a4.z, b4.y, acc[2][1]);
      acc[2][2] = fmaf(a4.z, b4.z, acc[2][2]); acc[2][3] = fmaf(a4.z, b4.w, acc[2][3]);
      acc[3][0] = fmaf(a4.w, b4.x, acc[3][0]); acc[3][1] = fmaf(a4.w, b4.y, acc[3][1]);
      acc[3][2] = fmaf(a4.w, b4.z, acc[3][2]); acc[3][3] = fmaf(a4.w, b4.w, acc[3][3]);
    }
    __syncthreads();
  }
  float4 bv = *(const float4*)(bias + bn + tx * 4);
  #pragma unroll
  for (int i = 0; i < 4; i++){
    size_t m = (size_t)bm + ty * 4 + i;
    float4 o = make_float4(acc[i][0] + bv.x, acc[i][1] + bv.y,
                           acc[i][2] + bv.z, acc[i][3] + bv.w);
    if (res){
      float4 rv = *(const float4*)(res + m * N + bn + tx * 4);
      o.x += rv.x; o.y += rv.y; o.z += rv.z; o.w += rv.w;
    }
    *(float4*)(C + m * N + bn + tx * 4) = o;
  }
}

// ---------------- scan stages ----------------
// Backbone stage: out[32, 16cols] = lecun_tanh( act[32,2048] @ W[:,c0:c0+16] + bias )
__device__ __forceinline__ void stage_bb(int cta, int tid, int t,
    const float* __restrict__ W, const float* __restrict__ bias,
    const float* __restrict__ src, bool concat, float* __restrict__ out,
    float* actS, float* wS)
{
  int b  = tid & 31, j  = tid >> 5;          // compute: batch row b, col-pair j (0..7)
  int lb = tid >> 3, lk = (tid & 7) * 8;     // act loader: row lb, k lk..lk+7
  int wk = tid >> 2, wq = (tid & 3) * 4;     // W loader: row wk (0..63), col wq..+3
  int c0 = cta * 16;
  float acc0 = 0.f, acc1 = 0.f;
  for (int k0 = 0; k0 < BBU_; k0 += KC){
    const float* sp;
    if (concat){
      sp = (k0 < D_) ? (src + ((size_t)lb * T_ + t) * D_ + k0)
                     : (g_h + (size_t)lb * U_ + (k0 - D_));
    } else {
      sp = src + (size_t)lb * BBU_ + k0;
    }
    float4 v0 = *(const float4*)(sp + lk);
    float4 v1 = *(const float4*)(sp + lk + 4);
    actS[(lk+0)*33+lb] = v0.x; actS[(lk+1)*33+lb] = v0.y;
    actS[(lk+2)*33+lb] = v0.z; actS[(lk+3)*33+lb] = v0.w;
    actS[(lk+4)*33+lb] = v1.x; actS[(lk+5)*33+lb] = v1.y;
    actS[(lk+6)*33+lb] = v1.z; actS[(lk+7)*33+lb] = v1.w;
    *(float4*)&wS[wk*16 + wq] = *(const float4*)(W + (size_t)(k0 + wk) * BBU_ + c0 + wq);
    __syncthreads();
    #pragma unroll
    for (int k = 0; k < KC; k++){
      float  a  = actS[k*33 + b];
      float2 wv = *(float2*)&wS[k*16 + j*2];   // adjacent cols c0+2j, c0+2j+1
      acc0 = fmaf(a, wv.x, acc0);
      acc1 = fmaf(a, wv.y, acc1);
    }
    __syncthreads();
  }
  int c = c0 + 2*j;
  float v0 = acc0 + bias[c], v1 = acc1 + bias[c+1];
  float2 o = make_float2(1.7159f * tanhf(0.666f * v0),
                         1.7159f * tanhf(0.666f * v1));
  *(float2*)&out[(size_t)b * BBU_ + c] = o;
}

// Head stage: for 8 u-cols per CTA compute ff1/ff2/ta/tb dots, gate, write h and cfc_out
__device__ __forceinline__ void stage_head(int cta, int tid, int t,
    const float* __restrict__ wff1, const float* __restrict__ bff1,
    const float* __restrict__ wff2, const float* __restrict__ bff2,
    const float* __restrict__ wta,  const float* __restrict__ bta,
    const float* __restrict__ wtb,  const float* __restrict__ btb,
    const float* __restrict__ tsp, float* actS, float* wS)
{
  int b  = tid & 31, j  = tid >> 5;          // b batch, j = u-local (0..7)
  int lb = tid >> 3, lk = (tid & 7) * 8;
  int m  = tid >> 6, wkk = tid & 63;         // loader: matrix m (0..3), k-row wkk
  int u0 = cta * 8;
  const float* wsrc = (m == 0) ? wff1 : (m == 1) ? wff2 : (m == 2) ? wta : wtb;
  float a0 = 0.f, a1 = 0.f, a2 = 0.f, a3 = 0.f;
  for (int k0 = 0; k0 < BBU_; k0 += KC){
    const float* sp = g_bb1 + (size_t)lb * BBU_ + k0;
    float4 v0 = *(const float4*)(sp + lk);
    float4 v1 = *(const float4*)(sp + lk + 4);
    actS[(lk+0)*33+lb] = v0.x; actS[(lk+1)*33+lb] = v0.y;
    actS[(lk+2)*33+lb] = v0.z; actS[(lk+3)*33+lb] = v0.w;
    actS[(lk+4)*33+lb] = v1.x; actS[(lk+5)*33+lb] = v1.y;
    actS[(lk+6)*33+lb] = v1.z; actS[(lk+7)*33+lb] = v1.w;
    const float* wp = wsrc + (size_t)(k0 + wkk) * U_ + u0;
    *(float4*)&wS[(m*KC + wkk)*8]     = *(const float4*)wp;
    *(float4*)&wS[(m*KC + wkk)*8 + 4] = *(const float4*)(wp + 4);
    __syncthreads();
    #pragma unroll
    for (int k = 0; k < KC; k++){
      float a = actS[k*33 + b];
      a0 = fmaf(a, wS[(0*KC + k)*8 + j], a0);
      a1 = fmaf(a, wS[(1*KC + k)*8 + j], a1);
      a2 = fmaf(a, wS[(2*KC + k)*8 + j], a2);
      a3 = fmaf(a, wS[(3*KC + k)*8 + j], a3);
    }
    __syncthreads();
  }
  int u = u0 + j;
  float tsv = tsp[(size_t)b * T_ + t];
  float f1  = tanhf(a0 + bff1[u]);
  float f2  = tanhf(a1 + bff2[u]);
  float ta  = a2 + bta[u], tb = a3 + btb[u];
  float sig = 1.f / (1.f + expf(-(ta * tsv + tb)));
  float hn  = f1 * (1.f - sig) + sig * f2;
  g_h[(size_t)b * U_ + u] = hn;
  g_cfco[((size_t)b * T_ + t) * U_ + u] = hn;
}

// ---------------- persistent scan kernel (128 co-resident CTAs) ----------------
__global__ void __launch_bounds__(NTHR, 1) k_scan(
    const float* __restrict__ tsp,
    const float* __restrict__ bbw,  const float* __restrict__ bbb,
    const float* __restrict__ wff1, const float* __restrict__ bff1,
    const float* __restrict__ wff2, const float* __restrict__ bff2,
    const float* __restrict__ wta,  const float* __restrict__ bta,
    const float* __restrict__ wtb,  const float* __restrict__ btb,
    float* __restrict__ hf)
{
  __shared__ float actS[KC * 33];
  __shared__ float wS[4 * KC * 8];
  int tid = threadIdx.x, cta = blockIdx.x;
  unsigned nbar = 0;
  const float* W0 = bbw;
  const float* W1 = bbw + (size_t)BBU_ * BBU_;
  const float* b0 = bbb;
  const float* b1 = bbb + BBU_;
  for (int t = 0; t < T_; t++){
    stage_bb(cta, tid, t, W0, b0, g_cfcx, true,  g_bb0, actS, wS);
    grid_bar(++nbar * NBLK);
    stage_bb(cta, tid, t, W1, b1, g_bb0, false, g_bb1, actS, wS);
    grid_bar(++nbar * NBLK);
    stage_head(cta, tid, t, wff1, bff1, wff2, bff2, wta, bta, wtb, btb, tsp, actS, wS);
    grid_bar(++nbar * NBLK);
  }
  if (hf){
    for (int i = cta * NTHR + tid; i < B_ * U_; i += NBLK * NTHR) hf[i] = g_h[i];
  }
}

// ---------------- launch ----------------
extern "C" void kernel_launch(void* const* d_in, const int* in_sizes, int n_in,
                              void* d_out, int out_size){
  (void)in_sizes; (void)n_in;
  const float* x    = (const float*)d_in[0];
  const float* tsp  = (const float*)d_in[1];
  const float* hid  = (const float*)d_in[2];
  const float* nw   = (const float*)d_in[3];
  const float* nb   = (const float*)d_in[4];
  const float* w_in = (const float*)d_in[5];
  const float* b_in = (const float*)d_in[6];
  const float* bbw  = (const float*)d_in[7];
  const float* bbb  = (const float*)d_in[8];
  const float* wff1 = (const float*)d_in[9];
  const float* bff1 = (const float*)d_in[10];
  const float* wff2 = (const float*)d_in[11];
  const float* bff2 = (const float*)d_in[12];
  const float* wta  = (const float*)d_in[13];
  const float* bta  = (const float*)d_in[14];
  const float* wtb  = (const float*)d_in[15];
  const float* btb  = (const float*)d_in[16];
  const float* wout = (const float*)d_in[17];
  const float* bout = (const float*)d_in[18];
  float* out = (float*)d_out;

  void *xn_p, *cfcx_p, *cfco_p, *h_p, *bar_p;
  cudaGetSymbolAddress(&xn_p,   g_xn);
  cudaGetSymbolAddress(&cfcx_p, g_cfcx);
  cudaGetSymbolAddress(&cfco_p, g_cfco);
  cudaGetSymbolAddress(&h_p,    g_h);
  cudaGetSymbolAddress(&bar_p,  g_bar);

  cudaMemsetAsync(bar_p, 0, sizeof(unsigned), 0);
  cudaMemcpyAsync(h_p, hid, (size_t)B_ * U_ * sizeof(float),
                  cudaMemcpyDeviceToDevice, 0);

  k_ln<<<B_ * T_, 256>>>(x, nw, nb);

  k_gemm<<<dim3(D_ / 64, (B_ * T_) / 64), 256>>>(
      (const float*)xn_p, w_in, b_in, nullptr, (float*)cfcx_p,
      B_ * T_, D_, D_);

  float* hf = ((size_t)out_size >= (size_t)B_ * T_ * D_ + (size_t)B_ * U_)
                  ? out + (size_t)B_ * T_ * D_ : nullptr;
  k_scan<<<NBLK, NTHR>>>(tsp, bbw, bbb, wff1, bff1, wff2, bff2,
                         wta, bta, wtb, btb, hf);

  k_gemm<<<dim3(D_ / 64, (B_ * T_) / 64), 256>>>(
      (const float*)cfco_p, wout, bout, x, out,
      B_ * T_, U_, D_);
}

// round 5
// speedup vs baseline: 1.4373x; 1.4373x over previous
#include <cuda_runtime.h>
#include <cstddef>
#include <math.h>

#define B_ 32
#define T_ 512
#define D_ 1024
#define U_ 1024
#define BBU_ 2048
#define NBLK 128
#define NTHR 512

// ---------------- persistent scratch (device globals; no runtime alloc) ----------------
__device__ float g_xn[B_*T_*D_];      // layernormed x
__device__ float g_cfcx[B_*T_*D_];    // xn @ w_in + b_in   [b][t][d]
__device__ float g_cfcxT[B_*T_*D_];   // transposed         [t][d][b]
__device__ float g_cfco[B_*T_*U_];    // scan outputs       [b][t][u]
__device__ float g_h[U_*B_];          // recurrent state transposed [u][b]
__device__ float g_bb0[BBU_*B_];      // bb layer0 out transposed [c][b]
__device__ float g_bb1[BBU_*B_];      // bb layer1 out transposed [c][b]
__device__ unsigned g_bar;            // monotonic grid-barrier counter

// ---------------- grid barrier (monotonic counter) ----------------
__device__ __forceinline__ void grid_bar(unsigned target){
  __syncthreads();
  if (threadIdx.x == 0){
    __threadfence();                       // release: flush our stage writes
    atomicAdd(&g_bar, 1u);
    while (*((volatile unsigned*)&g_bar) < target) { __nanosleep(32); }
    __threadfence();                       // acquire: gpu-scope fence invalidates L1D
  }
  __syncthreads();
}

// ---------------- packed f32x2 helpers ----------------
__device__ __forceinline__ unsigned long long fma2(unsigned long long x,
                                                   unsigned long long y,
                                                   unsigned long long z){
  unsigned long long d;
  asm("fma.rn.f32x2 %0, %1, %2, %3;" : "=l"(d) : "l"(x), "l"(y), "l"(z));
  return d;
}

__device__ __forceinline__ unsigned long long pack2(float a){
  unsigned au = __float_as_uint(a);
  unsigned long long p;
  asm("mov.b64 %0, {%1, %1};" : "=l"(p) : "r"(au));
  return p;
}

__device__ __forceinline__ void unpack2(unsigned long long v, float& lo, float& hi){
  unsigned l, h;
  asm("mov.b64 {%0, %1}, %2;" : "=r"(l), "=r"(h) : "l"(v));
  lo = __uint_as_float(l); hi = __uint_as_float(h);
}

// ---------------- warp GEMM slice: 8 cols, all 32 b, nk k's ----------------
// actT: [k][32] starting at warp's k0;  W: row k0, col c0, row stride N
__device__ __forceinline__ void warp_mm8(const float* __restrict__ actT,
                                         const float* __restrict__ W, int N,
                                         int nk, int lane,
                                         unsigned long long acc[4]){
  #pragma unroll 4
  for (int k = 0; k < nk; k++){
    float a = actT[(size_t)k * 32 + lane];                 // coalesced 128B/warp
    unsigned long long ap = pack2(a);
    const double2* wp = (const double2*)(W + (size_t)k * N); // uniform addr: 1 req/warp
    double2 w0 = __ldg(wp);
    double2 w1 = __ldg(wp + 1);
    acc[0] = fma2(ap, __double_as_longlong(w0.x), acc[0]);
    acc[1] = fma2(ap, __double_as_longlong(w0.y), acc[1]);
    acc[2] = fma2(ap, __double_as_longlong(w1.x), acc[2]);
    acc[3] = fma2(ap, __double_as_longlong(w1.y), acc[3]);
  }
}

// ---------------- LayerNorm ----------------
__global__ void k_ln(const float* __restrict__ x, const float* __restrict__ gw,
                     const float* __restrict__ gb){
  int row = blockIdx.x;
  int tid = threadIdx.x;
  const float4* xr = (const float4*)(x + (size_t)row * D_);
  float4 v = xr[tid];
  float s = v.x + v.y + v.z + v.w;
  float q = v.x*v.x + v.y*v.y + v.z*v.z + v.w*v.w;
  #pragma unroll
  for (int o = 16; o > 0; o >>= 1){
    s += __shfl_xor_sync(0xffffffffu, s, o);
    q += __shfl_xor_sync(0xffffffffu, q, o);
  }
  __shared__ float ss[8], sq[8];
  if ((tid & 31) == 0){ ss[tid >> 5] = s; sq[tid >> 5] = q; }
  __syncthreads();
  if (tid == 0){
    float a = 0.f, c = 0.f;
    #pragma unroll
    for (int i = 0; i < 8; i++){ a += ss[i]; c += sq[i]; }
    ss[0] = a; sq[0] = c;
  }
  __syncthreads();
  float mu  = ss[0] * (1.0f / D_);
  float var = sq[0] * (1.0f / D_) - mu * mu;
  float r   = rsqrtf(var + 1e-5f);
  float4 wv = ((const float4*)gw)[tid];
  float4 bv = ((const float4*)gb)[tid];
  float4 o;
  o.x = (v.x - mu) * r * wv.x + bv.x;
  o.y = (v.y - mu) * r * wv.y + bv.y;
  o.z = (v.z - mu) * r * wv.z + bv.z;
  o.w = (v.w - mu) * r * wv.w + bv.w;
  ((float4*)(g_xn + (size_t)row * D_))[tid] = o;
}

// ---------------- generic fp32 SGEMM: C = A[M,K] @ W[K,N] + bias (+res) ----------------
__global__ void __launch_bounds__(256) k_gemm(
    const float* __restrict__ A, const float* __restrict__ W,
    const float* __restrict__ bias, const float* __restrict__ res,
    float* __restrict__ C, int M, int N, int K)
{
  __shared__ float As[16][64];
  __shared__ float Ws[16][64];
  int tid = threadIdx.x;
  int bn = blockIdx.x * 64, bm = blockIdx.y * 64;
  int tx = tid & 15, ty = tid >> 4;
  int lam = tid >> 2, lak = (tid & 3) * 4;
  int lwk = tid >> 4, lwn = (tid & 15) * 4;
  float acc[4][4] = {};
  for (int k0 = 0; k0 < K; k0 += 16){
    float4 av = *(const float4*)(A + (size_t)(bm + lam) * K + k0 + lak);
    As[lak+0][lam] = av.x; As[lak+1][lam] = av.y;
    As[lak+2][lam] = av.z; As[lak+3][lam] = av.w;
    *(float4*)&Ws[lwk][lwn] = *(const float4*)(W + (size_t)(k0 + lwk) * N + bn + lwn);
    __syncthreads();
    #pragma unroll
    for (int k = 0; k < 16; k++){
      float4 a4 = *(float4*)&As[k][ty * 4];
      float4 b4 = *(float4*)&Ws[k][tx * 4];
      acc[0][0] = fmaf(a4.x, b4.x, acc[0][0]); acc[0][1] = fmaf(a4.x, b4.y, acc[0][1]);
      acc[0][2] = fmaf(a4.x, b4.z, acc[0][2]); acc[0][3] = fmaf(a4.x, b4.w, acc[0][3]);
      acc[1][0] = fmaf(a4.y, b4.x, acc[1][0]); acc[1][1] = fmaf(a4.y, b4.y, acc[1][1]);
      acc[1][2] = fmaf(a4.y, b4.z, acc[1][2]); acc[1][3] = fmaf(a4.y, b4.w, acc[1][3]);
      acc[2][0] = fmaf(a4.z, b4.x, acc[2][0]); acc[2][1] = fmaf(a4.z, b4.y, acc[2][1]);
      acc[2][2] = fmaf(a4.z, b4.z, acc[2][2]); acc[2][3] = fmaf(a4.z, b4.w, acc[2][3]);
      acc[3][0] = fmaf(a4.w, b4.x, acc[3][0]); acc[3][1] = fmaf(a4.w, b4.y, acc[3][1]);
      acc[3][2] = fmaf(a4.w, b4.z, acc[3][2]); acc[3][3] = fmaf(a4.w, b4.w, acc[3][3]);
    }
    __syncthreads();
  }
  float4 bv = *(const float4*)(bias + bn + tx * 4);
  #pragma unroll
  for (int i = 0; i < 4; i++){
    size_t m = (size_t)bm + ty * 4 + i;
    float4 o = make_float4(acc[i][0] + bv.x, acc[i][1] + bv.y,
                           acc[i][2] + bv.z, acc[i][3] + bv.w);
    if (res){
      float4 rv = *(const float4*)(res + m * N + bn + tx * 4);
      o.x += rv.x; o.y += rv.y; o.z += rv.z; o.w += rv.w;
    }
    *(float4*)(C + m * N + bn + tx * 4) = o;
  }
}

// ---------------- transpose cfc_x [b][t][d] -> [t][d][b] ----------------
__global__ void k_transpose(){
  __shared__ float tile[32][33];
  int d0 = blockIdx.x * 32, t = blockIdx.y;
  int lane = threadIdx.x & 31, r = threadIdx.x >> 5;  // 256 threads: r = 0..7
  #pragma unroll
  for (int i = 0; i < 4; i++){
    int b = r * 4 + i;
    tile[b][lane] = g_cfcx[((size_t)b * T_ + t) * D_ + d0 + lane];
  }
  __syncthreads();
  #pragma unroll
  for (int i = 0; i < 4; i++){
    int d = r * 4 + i;
    g_cfcxT[((size_t)t * D_ + d0 + d) * 32 + lane] = tile[lane][d];
  }
}

// ---------------- init transposed hidden state ----------------
__global__ void k_initT(const float* __restrict__ hid){
  int i = blockIdx.x * 256 + threadIdx.x;   // 32768 = U_*B_
  int u = i >> 5, b = i & 31;
  g_h[i] = hid[(size_t)b * U_ + u];
}

// ---------------- persistent scan kernel (128 CTAs x 512 thr) ----------------
__global__ void __launch_bounds__(NTHR, 1) k_scan(
    const float* __restrict__ tsp,
    const float* __restrict__ bbw,  const float* __restrict__ bbb,
    const float* __restrict__ wff1, const float* __restrict__ bff1,
    const float* __restrict__ wff2, const float* __restrict__ bff2,
    const float* __restrict__ wta,  const float* __restrict__ bta,
    const float* __restrict__ wtb,  const float* __restrict__ btb,
    float* __restrict__ hf)
{
  __shared__ float red[8 * 16 * 33];   // 16896 B; head reuses (4*4*8*33 = same size)
  int tid = threadIdx.x, cta = blockIdx.x;
  int lane = tid & 31, w = tid >> 5;   // 16 warps
  unsigned nbar = 0;

  const float* W1 = bbw + (size_t)BBU_ * BBU_;
  const float* b1 = bbb + BBU_;

  for (int t = 0; t < T_; t++){
    // ======== bb layer 0: out[c][b] = lecun_tanh(concat(cfc_x_t, h) @ W0 + b0) ========
    {
      int g = w & 1, ks = w >> 1;                 // 2 col-groups x 8 k-slices
      int c0 = cta * 16 + g * 8, k0 = ks * 256;
      const float* act = (k0 < D_) ? (g_cfcxT + ((size_t)t * D_ + k0) * 32)
                                   : (g_h + (size_t)(k0 - D_) * 32);
      unsigned long long acc[4] = {0ull, 0ull, 0ull, 0ull};
      warp_mm8(act, bbw + (size_t)k0 * BBU_ + c0, BBU_, 256, lane, acc);
      #pragma unroll
      for (int i = 0; i < 4; i++){
        float lo, hi; unpack2(acc[i], lo, hi);
        red[(ks * 16 + g * 8 + 2*i    ) * 33 + lane] = lo;
        red[(ks * 16 + g * 8 + 2*i + 1) * 33 + lane] = hi;
      }
      __syncthreads();
      int b = tid & 31, cl = tid >> 5;            // 512 threads: 32b x 16c
      float s = 0.f;
      #pragma unroll
      for (int k2 = 0; k2 < 8; k2++) s += red[(k2 * 16 + cl) * 33 + b];
      s += bbb[cta * 16 + cl];
      g_bb0[(size_t)(cta * 16 + cl) * 32 + b] = 1.7159f * tanhf(0.666f * s);
    }
    grid_bar(++nbar * NBLK);

    // ======== bb layer 1 ========
    {
      int g = w & 1, ks = w >> 1;
      int c0 = cta * 16 + g * 8, k0 = ks * 256;
      unsigned long long acc[4] = {0ull, 0ull, 0ull, 0ull};
      warp_mm8(g_bb0 + (size_t)k0 * 32, W1 + (size_t)k0 * BBU_ + c0, BBU_, 256, lane, acc);
      #pragma unroll
      for (int i = 0; i < 4; i++){
        float lo, hi; unpack2(acc[i], lo, hi);
        red[(ks * 16 + g * 8 + 2*i    ) * 33 + lane] = lo;
        red[(ks * 16 + g * 8 + 2*i + 1) * 33 + lane] = hi;
      }
      __syncthreads();
      int b = tid & 31, cl = tid >> 5;
      float s = 0.f;
      #pragma unroll
      for (int k2 = 0; k2 < 8; k2++) s += red[(k2 * 16 + cl) * 33 + b];
      s += b1[cta * 16 + cl];
      g_bb1[(size_t)(cta * 16 + cl) * 32 + b] = 1.7159f * tanhf(0.666f * s);
    }
    grid_bar(++nbar * NBLK);

    // ======== head: ff1/ff2/ta/tb + gating ========
    {
      int m = w & 3, ks = w >> 2;                 // 4 matrices x 4 k-slices
      int u0 = cta * 8, k0 = ks * 512;
      const float* wsrc = (m == 0) ? wff1 : (m == 1) ? wff2 : (m == 2) ? wta : wtb;
      unsigned long long acc[4] = {0ull, 0ull, 0ull, 0ull};
      warp_mm8(g_bb1 + (size_t)k0 * 32, wsrc + (size_t)k0 * U_ + u0, U_, 512, lane, acc);
      #pragma unroll
      for (int i = 0; i < 4; i++){
        float lo, hi; unpack2(acc[i], lo, hi);
        red[((ks * 4 + m) * 8 + 2*i    ) * 33 + lane] = lo;
        red[((ks * 4 + m) * 8 + 2*i + 1) * 33 + lane] = hi;
      }
      __syncthreads();
      if (tid < 256){
        int b = tid & 31, uu = tid >> 5;          // 32b x 8u
        float s0 = 0.f, s1 = 0.f, s2 = 0.f, s3 = 0.f;
        #pragma unroll
        for (int k2 = 0; k2 < 4; k2++){
          s0 += red[((k2 * 4 + 0) * 8 + uu) * 33 + b];
          s1 += red[((k2 * 4 + 1) * 8 + uu) * 33 + b];
          s2 += red[((k2 * 4 + 2) * 8 + uu) * 33 + b];
          s3 += red[((k2 * 4 + 3) * 8 + uu) * 33 + b];
        }
        int u = u0 + uu;
        float f1  = tanhf(s0 + bff1[u]);
        float f2  = tanhf(s1 + bff2[u]);
        float tav = s2 + bta[u], tbv = s3 + btb[u];
        float ts  = tsp[(size_t)b * T_ + t];
        float sig = 1.f / (1.f + expf(-(tav * ts + tbv)));
        float hn  = f1 * (1.f - sig) + sig * f2;
        g_h[(size_t)u * 32 + b] = hn;
        g_cfco[((size_t)b * T_ + t) * U_ + u] = hn;
      }
    }
    grid_bar(++nbar * NBLK);
  }

  if (hf){
    for (int i = cta * NTHR + tid; i < B_ * U_; i += NBLK * NTHR){
      int b = i >> 10, u = i & 1023;              // hf is [b][u]
      hf[i] = g_h[(size_t)u * 32 + b];
    }
  }
}

// ---------------- launch ----------------
extern "C" void kernel_launch(void* const* d_in, const int* in_sizes, int n_in,
                              void* d_out, int out_size){
  (void)in_sizes; (void)n_in;
  const float* x    = (const float*)d_in[0];
  const float* tsp  = (const float*)d_in[1];
  const float* hid  = (const float*)d_in[2];
  const float* nw   = (const float*)d_in[3];
  const float* nb   = (const float*)d_in[4];
  const float* w_in = (const float*)d_in[5];
  const float* b_in = (const float*)d_in[6];
  const float* bbw  = (const float*)d_in[7];
  const float* bbb  = (const float*)d_in[8];
  const float* wff1 = (const float*)d_in[9];
  const float* bff1 = (const float*)d_in[10];
  const float* wff2 = (const float*)d_in[11];
  const float* bff2 = (const float*)d_in[12];
  const float* wta  = (const float*)d_in[13];
  const float* bta  = (const float*)d_in[14];
  const float* wtb  = (const float*)d_in[15];
  const float* btb  = (const float*)d_in[16];
  const float* wout = (const float*)d_in[17];
  const float* bout = (const float*)d_in[18];
  float* out = (float*)d_out;

  void *xn_p, *cfcx_p, *cfco_p, *bar_p;
  cudaGetSymbolAddress(&xn_p,   g_xn);
  cudaGetSymbolAddress(&cfcx_p, g_cfcx);
  cudaGetSymbolAddress(&cfco_p, g_cfco);
  cudaGetSymbolAddress(&bar_p,  g_bar);

  cudaMemsetAsync(bar_p, 0, sizeof(unsigned), 0);

  k_initT<<<(U_ * B_) / 256, 256>>>(hid);

  k_ln<<<B_ * T_, 256>>>(x, nw, nb);

  k_gemm<<<dim3(D_ / 64, (B_ * T_) / 64), 256>>>(
      (const float*)xn_p, w_in, b_in, nullptr, (float*)cfcx_p,
      B_ * T_, D_, D_);

  k_transpose<<<dim3(D_ / 32, T_), 256>>>();

  float* hf = ((size_t)out_size >= (size_t)B_ * T_ * D_ + (size_t)B_ * U_)
                  ? out + (size_t)B_ * T_ * D_ : nullptr;
  k_scan<<<NBLK, NTHR>>>(tsp, bbw, bbb, wff1, bff1, wff2, bff2,
                         wta, bta, wtb, btb, hf);

  k_gemm<<<dim3(D_ / 64, (B_ * T_) / 64), 256>>>(
      (const float*)cfco_p, wout, bout, x, out,
      B_ * T_, U_, D_);
}

// round 6
// speedup vs baseline: 2.5954x; 1.8058x over previous
#include <cuda_runtime.h>
#include <cstddef>
#include <math.h>
#include <stdint.h>

#define B_ 32
#define T_ 512
#define D_ 1024
#define U_ 1024
#define BBU_ 2048
#define NBLK 128
#define NTHR 512
#define N_ITEMS (T_ * 10)

// ---------------- persistent scratch (device globals; no runtime alloc) ----------------
__device__ float g_xn[B_*T_*D_];        // layernormed x
__device__ float g_cfcx[B_*T_*D_];      // xn @ w_in + b_in           [b][t][d]
__device__ float g_P0[B_*T_*BBU_];      // cfc_x @ W0[:1024]          [b*t][c]
__device__ float g_P0T[T_*BBU_*B_];     // transposed                 [t][c][b]
__device__ float g_cfco[B_*T_*U_];      // scan outputs               [b][t][u]
__device__ float g_h[U_*B_];            // hidden, pair layout [u/2][b][2]
__device__ float g_bb0[BBU_*B_];        // bb l0 out, pair layout [c/2][b][2]
__device__ float g_bb1[BBU_*B_];        // bb l1 out, pair layout
__device__ float g_pkA[NBLK*1024*16];   // packed W0h per-CTA slices (8MB)
__device__ float g_pkH[NBLK*2048*32];   // packed head weights per-CTA (32MB)
__device__ float g_zero[BBU_];          // zero bias
__device__ unsigned g_bar;              // grid-barrier counter

// ---------------- helpers ----------------
__device__ __forceinline__ unsigned sptr(const void* p){
  return (unsigned)__cvta_generic_to_shared(p);
}

__device__ __forceinline__ void grid_bar(unsigned target){
  __syncthreads();
  if (threadIdx.x == 0){
    __threadfence();
    atomicAdd(&g_bar, 1u);
    while (*((volatile unsigned*)&g_bar) < target) { __nanosleep(16); }
    __threadfence();                     // gpu fence -> CCTL.IVALL (L1 invalidate)
  }
  __syncthreads();
}

__device__ __forceinline__ unsigned long long fma2(unsigned long long x,
                                                   unsigned long long y,
                                                   unsigned long long z){
  unsigned long long d;
  asm("fma.rn.f32x2 %0, %1, %2, %3;" : "=l"(d) : "l"(x), "l"(y), "l"(z));
  return d;
}
__device__ __forceinline__ unsigned long long pack2(float a){
  unsigned au = __float_as_uint(a);
  unsigned long long p;
  asm("mov.b64 %0, {%1, %1};" : "=l"(p) : "r"(au));
  return p;
}
__device__ __forceinline__ void unpack2(unsigned long long v, float& lo, float& hi){
  unsigned l, h;
  asm("mov.b64 {%0, %1}, %2;" : "=r"(l), "=r"(h) : "l"(v));
  lo = __uint_as_float(l); hi = __uint_as_float(h);
}
#define LL(x) __double_as_longlong(x)

// mbarrier ops
__device__ __forceinline__ void mbar_init(unsigned mb){
  asm volatile("mbarrier.init.shared.b64 [%0], %1;" :: "r"(mb), "r"(1u) : "memory");
}
__device__ __forceinline__ void tma_issue(unsigned mb, unsigned dst, const float* src){
  asm volatile("mbarrier.arrive.expect_tx.shared.b64 _, [%0], %1;"
               :: "r"(mb), "r"(32768u) : "memory");
  asm volatile("cp.async.bulk.shared::cta.global.mbarrier::complete_tx::bytes "
               "[%0], [%1], %2, [%3];"
               :: "r"(dst), "l"(src), "r"(32768u), "r"(mb) : "memory");
}
__device__ __forceinline__ void mbar_wait(unsigned mb, unsigned ph){
  unsigned done;
  do {
    asm volatile(
      "{\n\t.reg .pred p;\n\t"
      "mbarrier.try_wait.parity.shared::cta.b64 p, [%1], %2, 0x989680;\n\t"
      "selp.b32 %0, 1, 0, p;\n\t}"
      : "=r"(done) : "r"(mb), "r"(ph) : "memory");
  } while (!done);
}

// ---------------- LayerNorm ----------------
__global__ void k_ln(const float* __restrict__ x, const float* __restrict__ gw,
                     const float* __restrict__ gb){
  int row = blockIdx.x;
  int tid = threadIdx.x;
  const float4* xr = (const float4*)(x + (size_t)row * D_);
  float4 v = xr[tid];
  float s = v.x + v.y + v.z + v.w;
  float q = v.x*v.x + v.y*v.y + v.z*v.z + v.w*v.w;
  #pragma unroll
  for (int o = 16; o > 0; o >>= 1){
    s += __shfl_xor_sync(0xffffffffu, s, o);
    q += __shfl_xor_sync(0xffffffffu, q, o);
  }
  __shared__ float ss[8], sq[8];
  if ((tid & 31) == 0){ ss[tid >> 5] = s; sq[tid >> 5] = q; }
  __syncthreads();
  if (tid == 0){
    float a = 0.f, c = 0.f;
    #pragma unroll
    for (int i = 0; i < 8; i++){ a += ss[i]; c += sq[i]; }
    ss[0] = a; sq[0] = c;
  }
  __syncthreads();
  float mu  = ss[0] * (1.0f / D_);
  float var = sq[0] * (1.0f / D_) - mu * mu;
  float r   = rsqrtf(var + 1e-5f);
  float4 wv = ((const float4*)gw)[tid];
  float4 bv = ((const float4*)gb)[tid];
  float4 o;
  o.x = (v.x - mu) * r * wv.x + bv.x;
  o.y = (v.y - mu) * r * wv.y + bv.y;
  o.z = (v.z - mu) * r * wv.z + bv.z;
  o.w = (v.w - mu) * r * wv.w + bv.w;
  ((float4*)(g_xn + (size_t)row * D_))[tid] = o;
}

// ---------------- generic fp32 SGEMM: C = A[M,K]@W[K,N] + bias (+res) ----------------
__global__ void __launch_bounds__(256) k_gemm(
    const float* __restrict__ A, const float* __restrict__ W,
    const float* __restrict__ bias, const float* __restrict__ res,
    float* __restrict__ C, int M, int N, int K)
{
  __shared__ float As[16][64];
  __shared__ float Ws[16][64];
  int tid = threadIdx.x;
  int bn = blockIdx.x * 64, bm = blockIdx.y * 64;
  int tx = tid & 15, ty = tid >> 4;
  int lam = tid >> 2, lak = (tid & 3) * 4;
  int lwk = tid >> 4, lwn = (tid & 15) * 4;
  float acc[4][4] = {};
  for (int k0 = 0; k0 < K; k0 += 16){
    float4 av = *(const float4*)(A + (size_t)(bm + lam) * K + k0 + lak);
    As[lak+0][lam] = av.x; As[lak+1][lam] = av.y;
    As[lak+2][lam] = av.z; As[lak+3][lam] = av.w;
    *(float4*)&Ws[lwk][lwn] = *(const float4*)(W + (size_t)(k0 + lwk) * N + bn + lwn);
    __syncthreads();
    #pragma unroll
    for (int k = 0; k < 16; k++){
      float4 a4 = *(float4*)&As[k][ty * 4];
      float4 b4 = *(float4*)&Ws[k][tx * 4];
      acc[0][0] = fmaf(a4.x, b4.x, acc[0][0]); acc[0][1] = fmaf(a4.x, b4.y, acc[0][1]);
      acc[0][2] = fmaf(a4.x, b4.z, acc[0][2]); acc[0][3] = fmaf(a4.x, b4.w, acc[0][3]);
      acc[1][0] = fmaf(a4.y, b4.x, acc[1][0]); acc[1][1] = fmaf(a4.y, b4.y, acc[1][1]);
      acc[1][2] = fmaf(a4.y, b4.z, acc[1][2]); acc[1][3] = fmaf(a4.y, b4.w, acc[1][3]);
      acc[2][0] = fmaf(a4.z, b4.x, acc[2][0]); acc[2][1] = fmaf(a4.z, b4.y, acc[2][1]);
      acc[2][2] = fmaf(a4.z, b4.z, acc[2][2]); acc[2][3] = fmaf(a4.z, b4.w, acc[2][3]);
      acc[3][0] = fmaf(a4.w, b4.x, acc[3][0]); acc[3][1] = fmaf(a4.w, b4.y, acc[3][1]);
      acc[3][2] = fmaf(a4.w, b4.z, acc[3][2]); acc[3][3] = fmaf(a4.w, b4.w, acc[3][3]);
    }
    __syncthreads();
  }
  float4 bv = *(const float4*)(bias + bn + tx * 4);
  #pragma unroll
  for (int i = 0; i < 4; i++){
    size_t m = (size_t)bm + ty * 4 + i;
    float4 o = make_float4(acc[i][0] + bv.x, acc[i][1] + bv.y,
                           acc[i][2] + bv.z, acc[i][3] + bv.w);
    if (res){
      float4 rv = *(const float4*)(res + m * N + bn + tx * 4);
      o.x += rv.x; o.y += rv.y; o.z += rv.z; o.w += rv.w;
    }
    *(float4*)(C + m * N + bn + tx * 4) = o;
  }
}

// ---------------- transpose P0 [b][t][2048] -> [t][c][b] ----------------
__global__ void k_transP0(){
  __shared__ float tile[32][33];
  int c0 = blockIdx.x * 32, t = blockIdx.y;
  int lane = threadIdx.x & 31, r = threadIdx.x >> 5;
  #pragma unroll
  for (int i = 0; i < 4; i++){
    int b = r * 4 + i;
    tile[b][lane] = g_P0[((size_t)b * T_ + t) * BBU_ + c0 + lane];
  }
  __syncthreads();
  #pragma unroll
  for (int i = 0; i < 4; i++){
    int c = r * 4 + i;
    g_P0T[((size_t)t * BBU_ + c0 + c) * 32 + lane] = tile[lane][c];
  }
}

// ---------------- init hidden (pair layout) ----------------
__global__ void k_initT(const float* __restrict__ hid){
  int i = blockIdx.x * 256 + threadIdx.x;   // 32768
  int u = i >> 5, b = i & 31;
  g_h[((u >> 1) << 6) + b * 2 + (u & 1)] = hid[(size_t)b * U_ + u];
}

// ---------------- pack streamed weights into per-CTA contiguous slices ----------------
#define NP4A (NBLK * 1024 * 4)
#define NP4H (NBLK * 2048 * 8)
__global__ void k_pack(const float* __restrict__ W0,
                       const float* __restrict__ wff1, const float* __restrict__ wff2,
                       const float* __restrict__ wta,  const float* __restrict__ wtb){
  int q = blockIdx.x * 256 + threadIdx.x;
  if (q < NP4A){
    int cta = q >> 12, rem = q & 4095;
    int k = rem >> 2, c4 = (rem & 3) << 2;
    *(float4*)&g_pkA[(((size_t)cta << 10) + k) * 16 + c4] =
        *(const float4*)&W0[(size_t)(1024 + k) * BBU_ + cta * 16 + c4];
  } else if (q < NP4A + NP4H){
    int q2 = q - NP4A;
    int cta = q2 >> 14, rem = q2 & 16383;
    int k = rem >> 3, g8 = rem & 7;
    int m = g8 >> 1, h4 = (g8 & 1) << 2;
    const float* wm = (m == 0) ? wff1 : (m == 1) ? wff2 : (m == 2) ? wta : wtb;
    *(float4*)&g_pkH[(((size_t)cta << 11) + k) * 32 + m * 8 + h4] =
        *(const float4*)&wm[(size_t)k * U_ + cta * 8 + h4];
  }
}

// ---------------- persistent scan kernel ----------------
// SMEM: sW1 131072 | win0 32768 | win1 32768 | red 16896 | mbar 2x8
#define SM_W1   0
#define SM_WIN0 131072
#define SM_WIN1 (131072 + 32768)
#define SM_RED  (131072 + 65536)
#define SM_MBAR (SM_RED + 16896)
#define SM_TOTAL (SM_MBAR + 64)

__global__ void __launch_bounds__(NTHR, 1) k_scan(
    const float* __restrict__ tsp,
    const float* __restrict__ bbw,  const float* __restrict__ bbb,
    const float* __restrict__ bff1, const float* __restrict__ bff2,
    const float* __restrict__ bta,  const float* __restrict__ btb,
    float* __restrict__ hf)
{
  extern __shared__ char smem[];
  float* sW1  = (float*)(smem + SM_W1);
  float* winf[2] = { (float*)(smem + SM_WIN0), (float*)(smem + SM_WIN1) };
  float* red  = (float*)(smem + SM_RED);
  unsigned mb[2] = { sptr(smem + SM_MBAR), sptr(smem + SM_MBAR + 8) };
  unsigned winu[2] = { sptr(smem + SM_WIN0), sptr(smem + SM_WIN1) };

  int tid = threadIdx.x, cta = blockIdx.x;
  int lane = tid & 31, w = tid >> 5;
  unsigned nbar = 0;
  const float* W1 = bbw + (size_t)BBU_ * BBU_;
  const float* b1 = bbb + BBU_;

  if (tid == 0){ mbar_init(mb[0]); mbar_init(mb[1]); }
  // load persistent W1 slice: sW1[k][16]
  for (int i = tid; i < 2048 * 4; i += NTHR){
    int k = i >> 2, c4 = (i & 3) << 2;
    *(float4*)&sW1[k * 16 + c4] = *(const float4*)&W1[(size_t)k * BBU_ + cta * 16 + c4];
  }
  __syncthreads();

  unsigned ph0 = 0, ph1 = 0;
  int it = 0;
  if (tid == 0){
    // item src: r<2 -> pkA chunk r ; else pkH chunk r-2
    tma_issue(mb[0], winu[0], g_pkA + ((size_t)cta << 10) * 16);
    tma_issue(mb[1], winu[1], g_pkA + (((size_t)cta << 10) + 512) * 16);
  }

  for (int t = 0; t < T_; t++){
    // ================= bb layer 0 (h-half; x-half precomputed in P0T) =================
    {
      unsigned long long acc[4] = {0ull,0ull,0ull,0ull};
      int g = w & 1, ks = w >> 1;
      #pragma unroll
      for (int c = 0; c < 2; c++){
        int buf = it & 1;
        unsigned phv = buf ? ph1 : ph0;
        mbar_wait(mb[buf], phv);
        if (buf) ph1 ^= 1; else ph0 ^= 1;
        const float* wb = winf[buf] + (ks * 64) * 16 + g * 8;
        const float* ap = g_h + (size_t)((c * 512 + ks * 64) >> 1) * 64 + lane * 2;
        #pragma unroll 8
        for (int kk2 = 0; kk2 < 32; kk2++){
          float2 av = *(const float2*)(ap + kk2 * 64);
          unsigned long long a0 = pack2(av.x), a1 = pack2(av.y);
          const float* wr = wb + kk2 * 32;
          double2 p0 = *(const double2*)(wr),      q0 = *(const double2*)(wr + 4);
          double2 p1 = *(const double2*)(wr + 16), q1 = *(const double2*)(wr + 20);
          acc[0] = fma2(a0, LL(p0.x), acc[0]); acc[1] = fma2(a0, LL(p0.y), acc[1]);
          acc[2] = fma2(a0, LL(q0.x), acc[2]); acc[3] = fma2(a0, LL(q0.y), acc[3]);
          acc[0] = fma2(a1, LL(p1.x), acc[0]); acc[1] = fma2(a1, LL(p1.y), acc[1]);
          acc[2] = fma2(a1, LL(q1.x), acc[2]); acc[3] = fma2(a1, LL(q1.y), acc[3]);
        }
        if (c == 1){
          #pragma unroll
          for (int i = 0; i < 4; i++){
            float lo, hi; unpack2(acc[i], lo, hi);
            red[(ks * 16 + g * 8 + 2*i    ) * 33 + lane] = lo;
            red[(ks * 16 + g * 8 + 2*i + 1) * 33 + lane] = hi;
          }
        }
        __syncthreads();
        if (tid == 0 && it + 2 < N_ITEMS){
          int ni = it + 2, r = ni % 10;
          const float* src = (r < 2)
              ? g_pkA + (((size_t)cta << 10) + r * 512) * 16
              : g_pkH + (((size_t)cta << 11) + (r - 2) * 256) * 32;
          tma_issue(mb[buf], winu[buf], src);
        }
        it++;
      }
      int b2 = tid & 31, cl = tid >> 5;
      float s = 0.f;
      #pragma unroll
      for (int k2 = 0; k2 < 8; k2++) s += red[(k2 * 16 + cl) * 33 + b2];
      int cc = cta * 16 + cl;
      s += g_P0T[((size_t)t * BBU_ + cc) * 32 + b2] + bbb[cc];
      g_bb0[((size_t)(cc >> 1)) * 64 + b2 * 2 + (cc & 1)] = 1.7159f * tanhf(0.666f * s);
    }
    grid_bar(++nbar * NBLK);

    // ================= bb layer 1 (weights persistent in SMEM) =================
    {
      unsigned long long acc[4] = {0ull,0ull,0ull,0ull};
      int g = w & 1, ks = w >> 1;
      const float* wb = sW1 + (ks * 256) * 16 + g * 8;
      const float* ap = g_bb0 + (size_t)((ks * 256) >> 1) * 64 + lane * 2;
      #pragma unroll 8
      for (int kk2 = 0; kk2 < 128; kk2++){
        float2 av = *(const float2*)(ap + kk2 * 64);
        unsigned long long a0 = pack2(av.x), a1 = pack2(av.y);
        const float* wr = wb + kk2 * 32;
        double2 p0 = *(const double2*)(wr),      q0 = *(const double2*)(wr + 4);
        double2 p1 = *(const double2*)(wr + 16), q1 = *(const double2*)(wr + 20);
        acc[0] = fma2(a0, LL(p0.x), acc[0]); acc[1] = fma2(a0, LL(p0.y), acc[1]);
        acc[2] = fma2(a0, LL(q0.x), acc[2]); acc[3] = fma2(a0, LL(q0.y), acc[3]);
        acc[0] = fma2(a1, LL(p1.x), acc[0]); acc[1] = fma2(a1, LL(p1.y), acc[1]);
        acc[2] = fma2(a1, LL(q1.x), acc[2]); acc[3] = fma2(a1, LL(q1.y), acc[3]);
      }
      #pragma unroll
      for (int i = 0; i < 4; i++){
        float lo, hi; unpack2(acc[i], lo, hi);
        red[(ks * 16 + g * 8 + 2*i    ) * 33 + lane] = lo;
        red[(ks * 16 + g * 8 + 2*i + 1) * 33 + lane] = hi;
      }
      __syncthreads();
      int b2 = tid & 31, cl = tid >> 5;
      float s = 0.f;
      #pragma unroll
      for (int k2 = 0; k2 < 8; k2++) s += red[(k2 * 16 + cl) * 33 + b2];
      int cc = cta * 16 + cl;
      s += b1[cc];
      g_bb1[((size_t)(cc >> 1)) * 64 + b2 * 2 + (cc & 1)] = 1.7159f * tanhf(0.666f * s);
    }
    grid_bar(++nbar * NBLK);

    // ================= head (weights streamed, 8 chunks) =================
    {
      unsigned long long acc[4] = {0ull,0ull,0ull,0ull};
      int m = w & 3, ks2 = w >> 2;
      #pragma unroll
      for (int c = 0; c < 8; c++){
        int buf = it & 1;
        unsigned phv = buf ? ph1 : ph0;
        mbar_wait(mb[buf], phv);
        if (buf) ph1 ^= 1; else ph0 ^= 1;
        const float* wb = winf[buf] + (ks2 * 64) * 32 + m * 8;
        const float* ap = g_bb1 + (size_t)((c * 256 + ks2 * 64) >> 1) * 64 + lane * 2;
        #pragma unroll 8
        for (int kk2 = 0; kk2 < 32; kk2++){
          float2 av = *(const float2*)(ap + kk2 * 64);
          unsigned long long a0 = pack2(av.x), a1 = pack2(av.y);
          const float* wr = wb + kk2 * 64;
          double2 p0 = *(const double2*)(wr),      q0 = *(const double2*)(wr + 4);
          double2 p1 = *(const double2*)(wr + 32), q1 = *(const double2*)(wr + 36);
          acc[0] = fma2(a0, LL(p0.x), acc[0]); acc[1] = fma2(a0, LL(p0.y), acc[1]);
          acc[2] = fma2(a0, LL(q0.x), acc[2]); acc[3] = fma2(a0, LL(q0.y), acc[3]);
          acc[0] = fma2(a1, LL(p1.x), acc[0]); acc[1] = fma2(a1, LL(p1.y), acc[1]);
          acc[2] = fma2(a1, LL(q1.x), acc[2]); acc[3] = fma2(a1, LL(q1.y), acc[3]);
        }
        if (c == 7){
          #pragma unroll
          for (int i = 0; i < 4; i++){
            float lo, hi; unpack2(acc[i], lo, hi);
            red[((ks2 * 4 + m) * 8 + 2*i    ) * 33 + lane] = lo;
            red[((ks2 * 4 + m) * 8 + 2*i + 1) * 33 + lane] = hi;
          }
        }
        __syncthreads();
        if (tid == 0 && it + 2 < N_ITEMS){
          int ni = it + 2, r = ni % 10;
          const float* src = (r < 2)
              ? g_pkA + (((size_t)cta << 10) + r * 512) * 16
              : g_pkH + (((size_t)cta << 11) + (r - 2) * 256) * 32;
          tma_issue(mb[buf], winu[buf], src);
        }
        it++;
      }
      if (tid < 256){
        int b2 = tid >> 3, uu = tid & 7;
        float s0 = 0.f, s1 = 0.f, s2 = 0.f, s3 = 0.f;
        #pragma unroll
        for (int k2 = 0; k2 < 4; k2++){
          s0 += red[((k2 * 4 + 0) * 8 + uu) * 33 + b2];
          s1 += red[((k2 * 4 + 1) * 8 + uu) * 33 + b2];
          s2 += red[((k2 * 4 + 2) * 8 + uu) * 33 + b2];
          s3 += red[((k2 * 4 + 3) * 8 + uu) * 33 + b2];
        }
        int u = cta * 8 + uu;
        float f1  = tanhf(s0 + bff1[u]);
        float f2  = tanhf(s1 + bff2[u]);
        float tav = s2 + bta[u], tbv = s3 + btb[u];
        float ts  = tsp[(size_t)b2 * T_ + t];
        float sig = 1.f / (1.f + expf(-(tav * ts + tbv)));
        float hn  = f1 * (1.f - sig) + sig * f2;
        g_h[((size_t)(u >> 1)) * 64 + b2 * 2 + (u & 1)] = hn;
        g_cfco[((size_t)b2 * T_ + t) * U_ + u] = hn;
      }
    }
    grid_bar(++nbar * NBLK);
  }

  if (hf){
    for (int i = cta * NTHR + tid; i < B_ * U_; i += NBLK * NTHR){
      int b = i >> 10, u = i & 1023;
      hf[i] = g_h[((size_t)(u >> 1)) * 64 + b * 2 + (u & 1)];
    }
  }
}

// ---------------- launch ----------------
extern "C" void kernel_launch(void* const* d_in, const int* in_sizes, int n_in,
                              void* d_out, int out_size){
  (void)in_sizes; (void)n_in;
  const float* x    = (const float*)d_in[0];
  const float* tsp  = (const float*)d_in[1];
  const float* hid  = (const float*)d_in[2];
  const float* nw   = (const float*)d_in[3];
  const float* nb   = (const float*)d_in[4];
  const float* w_in = (const float*)d_in[5];
  const float* b_in = (const float*)d_in[6];
  const float* bbw  = (const float*)d_in[7];
  const float* bbb  = (const float*)d_in[8];
  const float* wff1 = (const float*)d_in[9];
  const float* bff1 = (const float*)d_in[10];
  const float* wff2 = (const float*)d_in[11];
  const float* bff2 = (const float*)d_in[12];
  const float* wta  = (const float*)d_in[13];
  const float* bta  = (const float*)d_in[14];
  const float* wtb  = (const float*)d_in[15];
  const float* btb  = (const float*)d_in[16];
  const float* wout = (const float*)d_in[17];
  const float* bout = (const float*)d_in[18];
  float* out = (float*)d_out;

  static int smem_set = 0;
  if (!smem_set){
    cudaFuncSetAttribute(k_scan, cudaFuncAttributeMaxDynamicSharedMemorySize, SM_TOTAL);
    smem_set = 1;
  }

  void *xn_p, *cfcx_p, *P0_p, *cfco_p, *zero_p, *bar_p;
  cudaGetSymbolAddress(&xn_p,   g_xn);
  cudaGetSymbolAddress(&cfcx_p, g_cfcx);
  cudaGetSymbolAddress(&P0_p,   g_P0);
  cudaGetSymbolAddress(&cfco_p, g_cfco);
  cudaGetSymbolAddress(&zero_p, g_zero);
  cudaGetSymbolAddress(&bar_p,  g_bar);

  cudaMemsetAsync(bar_p, 0, sizeof(unsigned), 0);

  k_initT<<<(U_ * B_) / 256, 256>>>(hid);

  k_pack<<<(NP4A + NP4H + 255) / 256, 256>>>(bbw, wff1, wff2, wta, wtb);

  k_ln<<<B_ * T_, 256>>>(x, nw, nb);

  // cfc_x = xn @ w_in + b_in
  k_gemm<<<dim3(D_ / 64, (B_ * T_) / 64), 256>>>(
      (const float*)xn_p, w_in, b_in, nullptr, (float*)cfcx_p,
      B_ * T_, D_, D_);

  // P0 = cfc_x @ W0[:1024,:]  (x-half of bb layer 0, no bias)
  k_gemm<<<dim3(BBU_ / 64, (B_ * T_) / 64), 256>>>(
      (const float*)cfcx_p, bbw, (const float*)zero_p, nullptr, (float*)P0_p,
      B_ * T_, BBU_, D_);

  k_transP0<<<dim3(BBU_ / 32, T_), 256>>>();

  float* hf = ((size_t)out_size >= (size_t)B_ * T_ * D_ + (size_t)B_ * U_)
                  ? out + (size_t)B_ * T_ * D_ : nullptr;
  k_scan<<<NBLK, NTHR, SM_TOTAL>>>(tsp, bbw, bbb, bff1, bff2, bta, btb, hf);

  // y = x + cfc_out @ w_out + b_out
  k_gemm<<<dim3(D_ / 64, (B_ * T_) / 64), 256>>>(
      (const float*)cfco_p, wout, bout, x, out,
      B_ * T_, U_, D_);
}